// round 1
// baseline (speedup 1.0000x reference)
#include <cuda_runtime.h>
#include <math.h>

// Problem dims (fixed by the dataset)
#define BB  4
#define SS  2048
#define DD  512
#define HH  8
#define HD  64
#define MM  (BB*SS)          // 8192

// Scratch (allocation-free rule: __device__ globals)
__device__ float g_q  [(size_t)MM * DD];
__device__ float g_k  [(size_t)MM * DD];
__device__ float g_v  [(size_t)MM * DD];
__device__ float g_ctx[(size_t)MM * DD];
__device__ float g_attn[(size_t)BB * HH * SS * SS];   // 536.9 MB

// ---------------------------------------------------------------------------
// Generic SGEMM NN with optional bias:  C[M,N] = A[M,K] @ B[K,N] + bias
// All dims assumed multiples of the tile sizes (true for this problem).
// ---------------------------------------------------------------------------
template<int BM, int BN, int BK, int TM, int TN>
__global__ void __launch_bounds__((BM/TM)*(BN/TN))
sgemm_nn_bias(const float* __restrict__ A, int lda,
              const float* __restrict__ B, int ldb,
              const float* __restrict__ bias,
              float* __restrict__ C, int ldc,
              int M, int N, int K)
{
    constexpr int NT = (BM/TM)*(BN/TN);
    __shared__ float As[BK][BM + 4];   // transposed, padded
    __shared__ float Bs[BK][BN];

    const int tid = threadIdx.x;
    const int tx  = tid % (BN/TN);
    const int ty  = tid / (BN/TN);
    const int m0  = blockIdx.y * BM;
    const int n0  = blockIdx.x * BN;

    float acc[TM][TN] = {};

    for (int kt = 0; kt < K; kt += BK) {
        // A tile: BM x BK, store transposed As[k][m]
        #pragma unroll
        for (int i = tid; i < BM*BK/4; i += NT) {
            int r = i / (BK/4);
            int c = (i % (BK/4)) * 4;
            float4 v = *(const float4*)&A[(size_t)(m0 + r) * lda + kt + c];
            As[c+0][r] = v.x; As[c+1][r] = v.y;
            As[c+2][r] = v.z; As[c+3][r] = v.w;
        }
        // B tile: BK x BN, natural layout
        #pragma unroll
        for (int i = tid; i < BK*BN/4; i += NT) {
            int r = i / (BN/4);
            int c = (i % (BN/4)) * 4;
            *(float4*)&Bs[r][c] = *(const float4*)&B[(size_t)(kt + r) * ldb + n0 + c];
        }
        __syncthreads();

        #pragma unroll
        for (int kk = 0; kk < BK; kk++) {
            float af[TM], bf[TN];
            #pragma unroll
            for (int i = 0; i < TM; i++) af[i] = As[kk][ty*TM + i];
            #pragma unroll
            for (int j = 0; j < TN; j++) bf[j] = Bs[kk][tx*TN + j];
            #pragma unroll
            for (int i = 0; i < TM; i++)
                #pragma unroll
                for (int j = 0; j < TN; j++)
                    acc[i][j] += af[i] * bf[j];
        }
        __syncthreads();
    }

    #pragma unroll
    for (int i = 0; i < TM; i++) {
        int m = m0 + ty*TM + i;
        #pragma unroll
        for (int j = 0; j < TN; j += 4) {
            int n = n0 + tx*TN + j;
            float4 v;
            v.x = acc[i][j+0] + (bias ? bias[n+0] : 0.f);
            v.y = acc[i][j+1] + (bias ? bias[n+1] : 0.f);
            v.z = acc[i][j+2] + (bias ? bias[n+2] : 0.f);
            v.w = acc[i][j+3] + (bias ? bias[n+3] : 0.f);
            *(float4*)&C[(size_t)m * ldc + n] = v;
        }
    }
}

// ---------------------------------------------------------------------------
// Batched NT scores: P[bz][q,k] = scale * Q[b,q,h,:] . K[b,k,h,:]
// Q/K layout: [B*S, D] row-major, head slice at column h*HD.
// grid = (S/BN, S/BM, B*H)
// ---------------------------------------------------------------------------
template<int BM, int BN, int BK, int TM, int TN>
__global__ void __launch_bounds__((BM/TM)*(BN/TN))
attn_scores_nt(float scale)
{
    constexpr int NT = (BM/TM)*(BN/TN);
    __shared__ float As[BK][BM + 4];
    __shared__ float Bs[BK][BN + 4];

    const int bz = blockIdx.z;               // b*H + h
    const int b  = bz >> 3;
    const int h  = bz & 7;
    const float* Aq = g_q + (size_t)b * SS * DD + h * HD;
    const float* Bk = g_k + (size_t)b * SS * DD + h * HD;
    float*       Cp = g_attn + (size_t)bz * SS * SS;

    const int tid = threadIdx.x;
    const int tx  = tid % (BN/TN);
    const int ty  = tid / (BN/TN);
    const int m0  = blockIdx.y * BM;
    const int n0  = blockIdx.x * BN;

    float acc[TM][TN] = {};

    for (int kt = 0; kt < HD; kt += BK) {
        #pragma unroll
        for (int i = tid; i < BM*BK/4; i += NT) {
            int r = i / (BK/4);
            int c = (i % (BK/4)) * 4;
            float4 v = *(const float4*)&Aq[(size_t)(m0 + r) * DD + kt + c];
            As[c+0][r] = v.x; As[c+1][r] = v.y;
            As[c+2][r] = v.z; As[c+3][r] = v.w;
        }
        #pragma unroll
        for (int i = tid; i < BN*BK/4; i += NT) {
            int r = i / (BK/4);
            int c = (i % (BK/4)) * 4;
            float4 v = *(const float4*)&Bk[(size_t)(n0 + r) * DD + kt + c];
            Bs[c+0][r] = v.x; Bs[c+1][r] = v.y;
            Bs[c+2][r] = v.z; Bs[c+3][r] = v.w;
        }
        __syncthreads();

        #pragma unroll
        for (int kk = 0; kk < BK; kk++) {
            float af[TM], bf[TN];
            #pragma unroll
            for (int i = 0; i < TM; i++) af[i] = As[kk][ty*TM + i];
            #pragma unroll
            for (int j = 0; j < TN; j++) bf[j] = Bs[kk][tx*TN + j];
            #pragma unroll
            for (int i = 0; i < TM; i++)
                #pragma unroll
                for (int j = 0; j < TN; j++)
                    acc[i][j] += af[i] * bf[j];
        }
        __syncthreads();
    }

    #pragma unroll
    for (int i = 0; i < TM; i++) {
        int m = m0 + ty*TM + i;
        #pragma unroll
        for (int j = 0; j < TN; j += 4) {
            int n = n0 + tx*TN + j;
            float4 v;
            v.x = acc[i][j+0] * scale;
            v.y = acc[i][j+1] * scale;
            v.z = acc[i][j+2] * scale;
            v.w = acc[i][j+3] * scale;
            *(float4*)&Cp[(size_t)m * SS + n] = v;
        }
    }
}

// ---------------------------------------------------------------------------
// Softmax over k + head-mean.  One block per (b, q).  In-place probs,
// writes avg_attn[b,q,:] to d_out second region.
// ---------------------------------------------------------------------------
__device__ __forceinline__ float blk_reduce(float v, bool is_max)
{
    __shared__ float sm[8];
    #pragma unroll
    for (int o = 16; o > 0; o >>= 1) {
        float w = __shfl_xor_sync(0xffffffffu, v, o);
        v = is_max ? fmaxf(v, w) : (v + w);
    }
    if ((threadIdx.x & 31) == 0) sm[threadIdx.x >> 5] = v;
    __syncthreads();
    float r = sm[0];
    #pragma unroll
    for (int i = 1; i < 8; i++) r = is_max ? fmaxf(r, sm[i]) : (r + sm[i]);
    __syncthreads();
    return r;
}

__global__ void __launch_bounds__(256)
softmax_avg_kernel(float* __restrict__ avg_out)
{
    const int bq  = blockIdx.x;            // 0 .. B*S-1
    const int b   = bq / SS;
    const int q   = bq % SS;
    const int tid = threadIdx.x;
    constexpr int NPT = SS / 256;          // 8

    float av[NPT];
    #pragma unroll
    for (int j = 0; j < NPT; j++) av[j] = 0.f;

    for (int h = 0; h < HH; h++) {
        float* row = g_attn + (((size_t)(b*HH + h)) * SS + q) * SS;
        float v[NPT];
        float m = -INFINITY;
        #pragma unroll
        for (int j = 0; j < NPT; j++) {
            v[j] = row[tid + j*256];
            m = fmaxf(m, v[j]);
        }
        m = blk_reduce(m, true);
        float s = 0.f;
        #pragma unroll
        for (int j = 0; j < NPT; j++) {
            v[j] = __expf(v[j] - m);
            s += v[j];
        }
        s = blk_reduce(s, false);
        float inv = 1.f / s;
        #pragma unroll
        for (int j = 0; j < NPT; j++) {
            float p = v[j] * inv;
            row[tid + j*256] = p;
            av[j] += p * (1.0f / HH);
        }
    }
    float* arow = avg_out + ((size_t)b * SS + q) * SS;
    #pragma unroll
    for (int j = 0; j < NPT; j++) arow[tid + j*256] = av[j];
}

// ---------------------------------------------------------------------------
// Batched NN ctx: Ctx[b,q,h,:] = P[bz] @ V[b,:,h,:]   (M=S, N=HD, K=S)
// grid = (1, S/BM, B*H)
// ---------------------------------------------------------------------------
template<int BM, int BN, int BK, int TM, int TN>
__global__ void __launch_bounds__((BM/TM)*(BN/TN))
attn_ctx_nn()
{
    constexpr int NT = (BM/TM)*(BN/TN);
    __shared__ float As[BK][BM + 4];
    __shared__ float Bs[BK][BN];

    const int bz = blockIdx.z;
    const int b  = bz >> 3;
    const int h  = bz & 7;
    const float* Ap = g_attn + (size_t)bz * SS * SS;          // lda = SS
    const float* Bv = g_v    + (size_t)b * SS * DD + h * HD;  // ldb = DD
    float*       Cc = g_ctx  + (size_t)b * SS * DD + h * HD;  // ldc = DD

    const int tid = threadIdx.x;
    const int tx  = tid % (BN/TN);
    const int ty  = tid / (BN/TN);
    const int m0  = blockIdx.y * BM;

    float acc[TM][TN] = {};

    for (int kt = 0; kt < SS; kt += BK) {
        #pragma unroll
        for (int i = tid; i < BM*BK/4; i += NT) {
            int r = i / (BK/4);
            int c = (i % (BK/4)) * 4;
            float4 v = *(const float4*)&Ap[(size_t)(m0 + r) * SS + kt + c];
            As[c+0][r] = v.x; As[c+1][r] = v.y;
            As[c+2][r] = v.z; As[c+3][r] = v.w;
        }
        #pragma unroll
        for (int i = tid; i < BK*BN/4; i += NT) {
            int r = i / (BN/4);
            int c = (i % (BN/4)) * 4;
            *(float4*)&Bs[r][c] = *(const float4*)&Bv[(size_t)(kt + r) * DD + c];
        }
        __syncthreads();

        #pragma unroll
        for (int kk = 0; kk < BK; kk++) {
            float af[TM], bf[TN];
            #pragma unroll
            for (int i = 0; i < TM; i++) af[i] = As[kk][ty*TM + i];
            #pragma unroll
            for (int j = 0; j < TN; j++) bf[j] = Bs[kk][tx*TN + j];
            #pragma unroll
            for (int i = 0; i < TM; i++)
                #pragma unroll
                for (int j = 0; j < TN; j++)
                    acc[i][j] += af[i] * bf[j];
        }
        __syncthreads();
    }

    #pragma unroll
    for (int i = 0; i < TM; i++) {
        int m = m0 + ty*TM + i;
        #pragma unroll
        for (int j = 0; j < TN; j += 4) {
            int n = tx*TN + j;
            float4 v;
            v.x = acc[i][j+0];
            v.y = acc[i][j+1];
            v.z = acc[i][j+2];
            v.w = acc[i][j+3];
            *(float4*)&Cc[(size_t)m * DD + n] = v;
        }
    }
}

// ---------------------------------------------------------------------------
extern "C" void kernel_launch(void* const* d_in, const int* in_sizes, int n_in,
                              void* d_out, int out_size)
{
    const float* x  = (const float*)d_in[0];
    const float* Wq = (const float*)d_in[1];
    const float* bq = (const float*)d_in[2];
    const float* Wk = (const float*)d_in[3];
    const float* bk = (const float*)d_in[4];
    const float* Wv = (const float*)d_in[5];
    const float* bv = (const float*)d_in[6];
    const float* Wo = (const float*)d_in[7];
    const float* bo = (const float*)d_in[8];

    float* out = (float*)d_out;                       // [B,S,D]
    float* avg = out + (size_t)BB * SS * DD;          // [B,S,S]

    float *pq, *pk, *pv, *pctx;
    cudaGetSymbolAddress((void**)&pq,   g_q);
    cudaGetSymbolAddress((void**)&pk,   g_k);
    cudaGetSymbolAddress((void**)&pv,   g_v);
    cudaGetSymbolAddress((void**)&pctx, g_ctx);

    dim3 blk(256);

    // 1) QKV projections: [8192,512] = x @ W + b
    dim3 g1(DD/128, MM/128);
    sgemm_nn_bias<128,128,16,8,8><<<g1, blk>>>(x, DD, Wq, DD, bq, pq, DD, MM, DD, DD);
    sgemm_nn_bias<128,128,16,8,8><<<g1, blk>>>(x, DD, Wk, DD, bk, pk, DD, MM, DD, DD);
    sgemm_nn_bias<128,128,16,8,8><<<g1, blk>>>(x, DD, Wv, DD, bv, pv, DD, MM, DD, DD);

    // 2) scores: P = scale * Q K^T, batched over B*H
    dim3 g2(SS/128, SS/128, BB*HH);
    attn_scores_nt<128,128,16,8,8><<<g2, blk>>>(1.0f / 8.0f);   // 1/sqrt(64)

    // 3) softmax over k + head-mean -> avg_attn
    softmax_avg_kernel<<<BB*SS, 256>>>(avg);

    // 4) ctx = P @ V, batched over B*H
    dim3 g3(1, SS/128, BB*HH);
    attn_ctx_nn<128,64,16,8,4><<<g3, blk>>>();

    // 5) out = ctx @ Wo + bo
    sgemm_nn_bias<128,128,16,8,8><<<g1, blk>>>(pctx, DD, Wo, DD, bo, out, DD, MM, DD, DD);
}

// round 2
// speedup vs baseline: 1.4307x; 1.4307x over previous
#include <cuda_runtime.h>
#include <cuda_bf16.h>
#include <math.h>

// Problem dims (fixed by the dataset)
#define BB  4
#define SS  2048
#define DD  512
#define HH  8
#define HD  64
#define MM  (BB*SS)          // 8192
#define BKT 16               // K tile

// Scratch (allocation-free rule: __device__ globals)
__device__ float g_q  [(size_t)MM * DD];
__device__ float g_k  [(size_t)MM * DD];
__device__ float g_v  [(size_t)MM * DD];
__device__ float g_ctx[(size_t)MM * DD];
__device__ float g_attn[(size_t)BB * HH * SS * SS];   // 536.9 MB

// ---------------------------------------------------------------------------
// bf16 split helpers:  x ~= hi + lo, |x - hi - lo| <~ 2^-18 |x|
// ---------------------------------------------------------------------------
__device__ __forceinline__ void split2(float x0, float x1, unsigned& h, unsigned& l)
{
    __nv_bfloat162 hb = __floats2bfloat162_rn(x0, x1);
    float2 hf = __bfloat1622float2(hb);
    __nv_bfloat162 lb = __floats2bfloat162_rn(x0 - hf.x, x1 - hf.y);
    h = *reinterpret_cast<unsigned*>(&hb);
    l = *reinterpret_cast<unsigned*>(&lb);
}
__device__ __forceinline__ void split1(float x, __nv_bfloat16& h, __nv_bfloat16& l)
{
    h = __float2bfloat16_rn(x);
    l = __float2bfloat16_rn(x - __bfloat162float(h));
}

__device__ __forceinline__ void mma16816(float c[4],
    unsigned a0, unsigned a1, unsigned a2, unsigned a3,
    unsigned b0, unsigned b1)
{
    asm volatile(
        "mma.sync.aligned.m16n8k16.row.col.f32.bf16.bf16.f32 "
        "{%0,%1,%2,%3},{%4,%5,%6,%7},{%8,%9},{%0,%1,%2,%3};"
        : "+f"(c[0]), "+f"(c[1]), "+f"(c[2]), "+f"(c[3])
        : "r"(a0), "r"(a1), "r"(a2), "r"(a3), "r"(b0), "r"(b1));
}

// ---------------------------------------------------------------------------
// Unified tensor-core GEMM (bf16x3 split, fp32 accumulate):
//   C[M,N] = scale * A @ op(B) + bias
// A row-major [M,K] (lda), B either [K,N] (NN) or [N,K] (NT, TRANS_B).
// Batched over blockIdx.z = b*8+h with independent strides.
// BM=128, 256 threads = 8 warps (2 x 4), warp tile (64 x BN/4).
// ---------------------------------------------------------------------------
template<int BM, int BN, bool TRANS_B, bool HAS_BIAS>
__global__ void __launch_bounds__(256)
mma_gemm(const float* __restrict__ A, int lda, long long sAb, long long sAh,
         const float* __restrict__ B, int ldb, long long sBb, long long sBh,
         const float* __restrict__ bias,
         float* __restrict__ C, int ldc, long long sCb, long long sCh,
         int K, float scale)
{
    constexpr int LDK = BKT + 2;                 // bf16 elems per smem row (+4B pad)
    constexpr int WM  = BM / 2;                  // 64
    constexpr int WN  = BN / 4;                  // 32 or 16
    constexpr int MT  = WM / 16;                 // 4
    constexpr int NT_ = WN / 8;                  // 4 or 2
    constexpr int A_VECS = BM * BKT / 4 / 256;   // 2
    constexpr int B_VECS = BN * BKT / 4 / 256;   // 2 or 1

    __shared__ __nv_bfloat16 Ah[BM][LDK], Al[BM][LDK];
    __shared__ __nv_bfloat16 Bh[BN][LDK], Bl[BN][LDK];

    const int z = blockIdx.z;
    const int b = z >> 3, h = z & 7;
    A += (long long)b * sAb + (long long)h * sAh;
    B += (long long)b * sBb + (long long)h * sBh;
    C += (long long)b * sCb + (long long)h * sCh;

    const int tid   = threadIdx.x;
    const int warp  = tid >> 5;
    const int lane  = tid & 31;
    const int g     = lane >> 2;       // groupID
    const int tq    = lane & 3;        // thread-in-quad
    const int warpM = warp >> 2;       // 0..1
    const int warpN = warp & 3;        // 0..3
    const int m0    = blockIdx.y * BM;
    const int n0    = blockIdx.x * BN;

    float acc[MT][NT_][4] = {};

    float4 pa[A_VECS], pb[B_VECS];

    // ---- tile loaders (gmem -> regs) ----
    auto load_a = [&](int kt) {
        #pragma unroll
        for (int j = 0; j < A_VECS; j++) {
            int idx = tid + j * 256;
            int r = idx >> 2;           // BKT/4 = 4 vecs per row
            int c = (idx & 3) << 2;
            pa[j] = *(const float4*)&A[(size_t)(m0 + r) * lda + kt + c];
        }
    };
    auto load_b = [&](int kt) {
        if (TRANS_B) {
            #pragma unroll
            for (int j = 0; j < B_VECS; j++) {
                int idx = tid + j * 256;
                int r = idx >> 2;
                int c = (idx & 3) << 2;
                pb[j] = *(const float4*)&B[(size_t)(n0 + r) * ldb + kt + c];
            }
        } else {
            #pragma unroll
            for (int j = 0; j < B_VECS; j++) {
                int idx = tid + j * 256;
                int r = idx / (BN / 4);
                int c = (idx % (BN / 4)) << 2;
                pb[j] = *(const float4*)&B[(size_t)(kt + r) * ldb + n0 + c];
            }
        }
    };
    // ---- regs -> smem (with bf16 hi/lo split) ----
    auto store_a = [&]() {
        #pragma unroll
        for (int j = 0; j < A_VECS; j++) {
            int idx = tid + j * 256;
            int r = idx >> 2;
            int c = (idx & 3) << 2;
            unsigned h01, l01, h23, l23;
            split2(pa[j].x, pa[j].y, h01, l01);
            split2(pa[j].z, pa[j].w, h23, l23);
            *(unsigned*)&Ah[r][c]     = h01;
            *(unsigned*)&Ah[r][c + 2] = h23;
            *(unsigned*)&Al[r][c]     = l01;
            *(unsigned*)&Al[r][c + 2] = l23;
        }
    };
    auto store_b = [&]() {
        if (TRANS_B) {
            #pragma unroll
            for (int j = 0; j < B_VECS; j++) {
                int idx = tid + j * 256;
                int r = idx >> 2;
                int c = (idx & 3) << 2;
                unsigned h01, l01, h23, l23;
                split2(pb[j].x, pb[j].y, h01, l01);
                split2(pb[j].z, pb[j].w, h23, l23);
                *(unsigned*)&Bh[r][c]     = h01;
                *(unsigned*)&Bh[r][c + 2] = h23;
                *(unsigned*)&Bl[r][c]     = l01;
                *(unsigned*)&Bl[r][c + 2] = l23;
            }
        } else {
            #pragma unroll
            for (int j = 0; j < B_VECS; j++) {
                int idx = tid + j * 256;
                int r = idx / (BN / 4);
                int c = (idx % (BN / 4)) << 2;
                float v[4] = { pb[j].x, pb[j].y, pb[j].z, pb[j].w };
                #pragma unroll
                for (int q = 0; q < 4; q++) {
                    __nv_bfloat16 hh, ll;
                    split1(v[q], hh, ll);
                    Bh[c + q][r] = hh;
                    Bl[c + q][r] = ll;
                }
            }
        }
    };

    const int NKT = K / BKT;
    load_a(0); load_b(0);
    store_a(); store_b();
    __syncthreads();

    for (int kt = 0; kt < NKT; kt++) {
        if (kt + 1 < NKT) { load_a((kt + 1) * BKT); load_b((kt + 1) * BKT); }

        // fragment loads
        unsigned afh[MT][4], afl[MT][4], bfh[NT_][2], bfl[NT_][2];
        #pragma unroll
        for (int mt = 0; mt < MT; mt++) {
            int r0 = warpM * WM + mt * 16 + g;
            afh[mt][0] = *(unsigned*)&Ah[r0][2 * tq];
            afh[mt][1] = *(unsigned*)&Ah[r0 + 8][2 * tq];
            afh[mt][2] = *(unsigned*)&Ah[r0][2 * tq + 8];
            afh[mt][3] = *(unsigned*)&Ah[r0 + 8][2 * tq + 8];
            afl[mt][0] = *(unsigned*)&Al[r0][2 * tq];
            afl[mt][1] = *(unsigned*)&Al[r0 + 8][2 * tq];
            afl[mt][2] = *(unsigned*)&Al[r0][2 * tq + 8];
            afl[mt][3] = *(unsigned*)&Al[r0 + 8][2 * tq + 8];
        }
        #pragma unroll
        for (int nt = 0; nt < NT_; nt++) {
            int c0 = warpN * WN + nt * 8 + g;
            bfh[nt][0] = *(unsigned*)&Bh[c0][2 * tq];
            bfh[nt][1] = *(unsigned*)&Bh[c0][2 * tq + 8];
            bfl[nt][0] = *(unsigned*)&Bl[c0][2 * tq];
            bfl[nt][1] = *(unsigned*)&Bl[c0][2 * tq + 8];
        }

        #pragma unroll
        for (int mt = 0; mt < MT; mt++)
            #pragma unroll
            for (int nt = 0; nt < NT_; nt++) {
                mma16816(acc[mt][nt], afh[mt][0], afh[mt][1], afh[mt][2], afh[mt][3],
                         bfh[nt][0], bfh[nt][1]);
                mma16816(acc[mt][nt], afh[mt][0], afh[mt][1], afh[mt][2], afh[mt][3],
                         bfl[nt][0], bfl[nt][1]);
                mma16816(acc[mt][nt], afl[mt][0], afl[mt][1], afl[mt][2], afl[mt][3],
                         bfh[nt][0], bfh[nt][1]);
            }

        if (kt + 1 < NKT) {
            __syncthreads();
            store_a(); store_b();
            __syncthreads();
        }
    }

    // epilogue
    #pragma unroll
    for (int mt = 0; mt < MT; mt++) {
        int r0 = m0 + warpM * WM + mt * 16 + g;
        #pragma unroll
        for (int nt = 0; nt < NT_; nt++) {
            int c = n0 + warpN * WN + nt * 8 + 2 * tq;
            float bx = 0.f, by = 0.f;
            if (HAS_BIAS) { bx = bias[c]; by = bias[c + 1]; }
            float2 v0, v1;
            v0.x = acc[mt][nt][0] * scale + bx;
            v0.y = acc[mt][nt][1] * scale + by;
            v1.x = acc[mt][nt][2] * scale + bx;
            v1.y = acc[mt][nt][3] * scale + by;
            *(float2*)&C[(size_t)r0 * ldc + c]       = v0;
            *(float2*)&C[(size_t)(r0 + 8) * ldc + c] = v1;
        }
    }
}

// ---------------------------------------------------------------------------
// Softmax over k + head-mean.  One block per (b, q).  In-place probs,
// writes avg_attn[b,q,:] to d_out second region.
// ---------------------------------------------------------------------------
__device__ __forceinline__ float blk_reduce(float v, bool is_max)
{
    __shared__ float sm[8];
    #pragma unroll
    for (int o = 16; o > 0; o >>= 1) {
        float w = __shfl_xor_sync(0xffffffffu, v, o);
        v = is_max ? fmaxf(v, w) : (v + w);
    }
    if ((threadIdx.x & 31) == 0) sm[threadIdx.x >> 5] = v;
    __syncthreads();
    float r = sm[0];
    #pragma unroll
    for (int i = 1; i < 8; i++) r = is_max ? fmaxf(r, sm[i]) : (r + sm[i]);
    __syncthreads();
    return r;
}

__global__ void __launch_bounds__(256)
softmax_avg_kernel(float* __restrict__ avg_out)
{
    const int bq  = blockIdx.x;            // 0 .. B*S-1
    const int b   = bq / SS;
    const int q   = bq % SS;
    const int tid = threadIdx.x;
    constexpr int NPT = SS / 256;          // 8

    float av[NPT];
    #pragma unroll
    for (int j = 0; j < NPT; j++) av[j] = 0.f;

    for (int h = 0; h < HH; h++) {
        float* row = g_attn + (((size_t)(b*HH + h)) * SS + q) * SS;
        float v[NPT];
        float m = -INFINITY;
        #pragma unroll
        for (int j = 0; j < NPT; j++) {
            v[j] = row[tid + j*256];
            m = fmaxf(m, v[j]);
        }
        m = blk_reduce(m, true);
        float s = 0.f;
        #pragma unroll
        for (int j = 0; j < NPT; j++) {
            v[j] = __expf(v[j] - m);
            s += v[j];
        }
        s = blk_reduce(s, false);
        float inv = 1.f / s;
        #pragma unroll
        for (int j = 0; j < NPT; j++) {
            float p = v[j] * inv;
            row[tid + j*256] = p;
            av[j] += p * (1.0f / HH);
        }
    }
    float* arow = avg_out + ((size_t)b * SS + q) * SS;
    #pragma unroll
    for (int j = 0; j < NPT; j++) arow[tid + j*256] = av[j];
}

// ---------------------------------------------------------------------------
extern "C" void kernel_launch(void* const* d_in, const int* in_sizes, int n_in,
                              void* d_out, int out_size)
{
    const float* x  = (const float*)d_in[0];
    const float* Wq = (const float*)d_in[1];
    const float* bq = (const float*)d_in[2];
    const float* Wk = (const float*)d_in[3];
    const float* bk = (const float*)d_in[4];
    const float* Wv = (const float*)d_in[5];
    const float* bv = (const float*)d_in[6];
    const float* Wo = (const float*)d_in[7];
    const float* bo = (const float*)d_in[8];

    float* out = (float*)d_out;                       // [B,S,D]
    float* avg = out + (size_t)BB * SS * DD;          // [B,S,S]

    float *pq, *pk, *pv, *pctx, *pattn;
    cudaGetSymbolAddress((void**)&pq,    g_q);
    cudaGetSymbolAddress((void**)&pk,    g_k);
    cudaGetSymbolAddress((void**)&pv,    g_v);
    cudaGetSymbolAddress((void**)&pctx,  g_ctx);
    cudaGetSymbolAddress((void**)&pattn, g_attn);

    dim3 blk(256);
    const long long SD = (long long)SS * DD;
    const long long S2 = (long long)SS * SS;

    // 1) QKV projections: [8192,512] = x @ W + b   (NN, z=1)
    dim3 g1(DD/128, MM/128, 1);
    mma_gemm<128,128,false,true><<<g1, blk>>>(x, DD, 0, 0, Wq, DD, 0, 0, bq, pq,  DD, 0, 0, DD, 1.f);
    mma_gemm<128,128,false,true><<<g1, blk>>>(x, DD, 0, 0, Wk, DD, 0, 0, bk, pk,  DD, 0, 0, DD, 1.f);
    mma_gemm<128,128,false,true><<<g1, blk>>>(x, DD, 0, 0, Wv, DD, 0, 0, bv, pv,  DD, 0, 0, DD, 1.f);

    // 2) scores: P = scale * Q K^T  (NT, batched z = b*8+h)
    dim3 g2(SS/128, SS/128, BB*HH);
    mma_gemm<128,128,true,false><<<g2, blk>>>(pq, DD, SD, HD, pk, DD, SD, HD, nullptr,
                                              pattn, SS, 8*S2, S2, HD, 0.125f);

    // 3) softmax over k + head-mean -> avg_attn (probs in place)
    softmax_avg_kernel<<<BB*SS, 256>>>(avg);

    // 4) ctx = P @ V  (NN, batched)
    dim3 g3(1, SS/128, BB*HH);
    mma_gemm<128,64,false,false><<<g3, blk>>>(pattn, SS, 8*S2, S2, pv, DD, SD, HD, nullptr,
                                              pctx, DD, SD, HD, SS, 1.f);

    // 5) out = ctx @ Wo + bo
    mma_gemm<128,128,false,true><<<g1, blk>>>(pctx, DD, 0, 0, Wo, DD, 0, 0, bo, out, DD, 0, 0, DD, 1.f);
}